// round 5
// baseline (speedup 1.0000x reference)
#include <cuda_runtime.h>
#include <cstdint>
#include <cstddef>

#define BDIM 64
#define TDIM 512
#define DDIM 512
#define HDIM 1024
#define ODIM 512
#define G3   3072
#define MROWS 32768            // B*T
#define RCTA 64                // recurrence CTAs (single wave)
#define RJ   16                // hidden units per recurrence CTA

// Scratch (device globals are the sanctioned no-alloc workaround)
__device__ float g_xall[(size_t)MROWS * G3];        // x projection, 402 MB
__device__ float g_hbuf[2][BDIM * HDIM];            // h ping-pong (plain fp32)
__device__ unsigned g_hfrag[2][BDIM * HDIM];        // h ping-pong (tf32, A-fragment-major)
__device__ volatile unsigned g_count;               // global barrier counter

__device__ __forceinline__ unsigned f2tf32(float x) {
    unsigned r;
    asm("cvt.rna.tf32.f32 %0, %1;" : "=r"(r) : "f"(x));
    return r;
}

__device__ __forceinline__ void mma_tf32_k8(float* d,
    unsigned a0, unsigned a1, unsigned a2, unsigned a3,
    unsigned b0, unsigned b1)
{
    asm volatile(
        "mma.sync.aligned.m16n8k8.row.col.f32.tf32.tf32.f32 "
        "{%0,%1,%2,%3}, {%4,%5,%6,%7}, {%8,%9}, {%0,%1,%2,%3};\n"
        : "+f"(d[0]), "+f"(d[1]), "+f"(d[2]), "+f"(d[3])
        : "r"(a0), "r"(a1), "r"(a2), "r"(a3), "r"(b0), "r"(b1));
}

__device__ __forceinline__ float sigmoidf_(float x) {
    return 1.0f / (1.0f + __expf(-x));
}
__device__ __forceinline__ float tanhf_(float x) {
    x = fminf(fmaxf(x, -15.0f), 15.0f);
    float e = __expf(-2.0f * x);
    return (1.0f - e) / (1.0f + e);
}

// ---------------------------------------------------------------------------
// Generic NT GEMM: C[M,N] = A[M,K](rm) * B[N,K](rm)^T + bias[N]
// Tiles: BM=128, BN=128, BK=32; 256 threads; warp grid 4(m) x 2(n).
// tf32 m16n8k8 MMA; smem k-major, pad 132.
// ---------------------------------------------------------------------------
__global__ __launch_bounds__(256) void gemm_nt_kernel(
    const float* __restrict__ A, const float* __restrict__ B,
    const float* __restrict__ bias, float* __restrict__ C,
    int N, int K)
{
    __shared__ unsigned As[32][132];
    __shared__ unsigned Bs[32][132];
    const int tid  = threadIdx.x;
    const int lane = tid & 31;
    const int warp = tid >> 5;
    const int wm = warp & 3;
    const int wn = warp >> 2;
    const int g = lane >> 2;
    const int c = lane & 3;
    const int bm = blockIdx.y, bn = blockIdx.x;
    const float* Ab = A + (size_t)bm * 128 * K;
    const float* Bb = B + (size_t)bn * 128 * K;

    float acc[2][8][4];
#pragma unroll
    for (int i = 0; i < 2; i++)
#pragma unroll
        for (int j = 0; j < 8; j++)
#pragma unroll
            for (int e = 0; e < 4; e++) acc[i][j][e] = 0.0f;

    for (int k0 = 0; k0 < K; k0 += 32) {
        __syncthreads();
#pragma unroll
        for (int p = 0; p < 4; p++) {
            int flat = p * 256 + tid;
            int row = flat >> 3;
            int ks = (flat & 7) * 4;
            float4 va = *(const float4*)(Ab + (size_t)row * K + k0 + ks);
            As[ks + 0][row] = f2tf32(va.x);
            As[ks + 1][row] = f2tf32(va.y);
            As[ks + 2][row] = f2tf32(va.z);
            As[ks + 3][row] = f2tf32(va.w);
            float4 vb = *(const float4*)(Bb + (size_t)row * K + k0 + ks);
            Bs[ks + 0][row] = f2tf32(vb.x);
            Bs[ks + 1][row] = f2tf32(vb.y);
            Bs[ks + 2][row] = f2tf32(vb.z);
            Bs[ks + 3][row] = f2tf32(vb.w);
        }
        __syncthreads();
#pragma unroll
        for (int ks = 0; ks < 32; ks += 8) {
            unsigned a[2][4], b[8][2];
#pragma unroll
            for (int mt = 0; mt < 2; mt++) {
                int mb = wm * 32 + mt * 16;
                a[mt][0] = As[ks + c][mb + g];
                a[mt][1] = As[ks + c][mb + g + 8];
                a[mt][2] = As[ks + c + 4][mb + g];
                a[mt][3] = As[ks + c + 4][mb + g + 8];
            }
#pragma unroll
            for (int nt = 0; nt < 8; nt++) {
                int col = wn * 64 + nt * 8 + g;
                b[nt][0] = Bs[ks + c][col];
                b[nt][1] = Bs[ks + c + 4][col];
            }
#pragma unroll
            for (int mt = 0; mt < 2; mt++)
#pragma unroll
                for (int nt = 0; nt < 8; nt++)
                    mma_tf32_k8(acc[mt][nt], a[mt][0], a[mt][1], a[mt][2], a[mt][3],
                                b[nt][0], b[nt][1]);
        }
    }

#pragma unroll
    for (int mt = 0; mt < 2; mt++) {
        int row = bm * 128 + wm * 32 + mt * 16 + g;
#pragma unroll
        for (int nt = 0; nt < 8; nt++) {
            int col = bn * 128 + wn * 64 + nt * 8 + 2 * c;
            float b0 = bias[col], b1 = bias[col + 1];
            C[(size_t)row * N + col]           = acc[mt][nt][0] + b0;
            C[(size_t)row * N + col + 1]       = acc[mt][nt][1] + b1;
            C[(size_t)(row + 8) * N + col]     = acc[mt][nt][2] + b0;
            C[(size_t)(row + 8) * N + col + 1] = acc[mt][nt][3] + b1;
        }
    }
}

// ---------------------------------------------------------------------------
// Persistent GRU recurrence. 64 CTAs (single wave), 512 threads each.
// CTA owns RJ=16 hidden units -> per gate 2 n8 tiles (jh=0/1).
// Warps: mt = warp&3 (16 batch rows), kh = warp>>2 (K quarter, 32 k8-iters).
// Each warp loads ONE a-frag (LDG.128, .cg) per k8-iter and feeds 6 MMAs
// (3 gates x 2 jh) -> chip a-frag L2 traffic = 64 CTA x 256KB = 16MB/step.
// Wh resident in SMEM in B-frag order (192KB). 4-way K reduction via two
// conflict-free SMEM stages. One global barrier per step.
// ---------------------------------------------------------------------------
extern __shared__ unsigned rec_smem[];   // Whs[49152] + red[6400 floats]

__global__ __launch_bounds__(512, 1) void gru_rec_kernel(
    const float* __restrict__ Wh, const float* __restrict__ bh,
    float* __restrict__ hiddens)
{
    unsigned* Whs = rec_smem;                       // [kb128][gate3][jh2][lane32][2]
    float* red = (float*)(rec_smem + 49152);        // [buf2][mt4*lane32][25]
    const int tid  = threadIdx.x;
    const int lane = tid & 31;
    const int warp = tid >> 5;
    const int mt = warp & 3;        // batch quarter (16 rows)
    const int kh = warp >> 2;       // K quarter (0..3)
    const int g = lane >> 2, c = lane & 3;
    const int j0 = blockIdx.x * RJ;

    // Load Wh slice -> SMEM in B-fragment order (tf32), once.
    for (int flat = tid; flat < 128 * 6 * 32; flat += 512) {
        int kb = flat / 192, rem = flat % 192;
        int gi = rem >> 6;            // gate
        int jh = (rem >> 5) & 1;      // j-half
        int ln = rem & 31;
        int gg = ln >> 2, cc = ln & 3;
        const float* wp = Wh + (size_t)(gi * HDIM + j0 + jh * 8 + gg) * HDIM + kb * 8 + cc;
        Whs[flat * 2 + 0] = f2tf32(wp[0]);
        Whs[flat * 2 + 1] = f2tf32(wp[4]);
    }

    const int b0r = mt * 16 + g, b1r = b0r + 8;
    float bhv[3][2][2];               // [gate][jh][part]
#pragma unroll
    for (int gi = 0; gi < 3; gi++)
#pragma unroll
        for (int jh = 0; jh < 2; jh++) {
            int jj = j0 + jh * 8 + 2 * c;
            bhv[gi][jh][0] = bh[gi * HDIM + jj];
            bhv[gi][jh][1] = bh[gi * HDIM + jj + 1];
        }
    __syncthreads();

    for (int t = 0; t < TDIM; t++) {
        const int pp = t & 1;

        // Prefetch x_t and h_prev (latency hidden behind MMA loop). .cg for
        // h (written by other SMs this kernel); x written by a prior launch.
        float2 xv[3][2][2], hp[2][2];
        if (kh == 0) {
#pragma unroll
            for (int gi = 0; gi < 3; gi++)
#pragma unroll
                for (int jh = 0; jh < 2; jh++) {
                    int jj = j0 + jh * 8 + 2 * c;
                    xv[gi][jh][0] = *(const float2*)&g_xall[((size_t)b0r * TDIM + t) * G3 + gi * HDIM + jj];
                    xv[gi][jh][1] = *(const float2*)&g_xall[((size_t)b1r * TDIM + t) * G3 + gi * HDIM + jj];
                }
#pragma unroll
            for (int jh = 0; jh < 2; jh++) {
                int jj = j0 + jh * 8 + 2 * c;
                hp[jh][0] = __ldcg((const float2*)&g_hbuf[pp][b0r * HDIM + jj]);
                hp[jh][1] = __ldcg((const float2*)&g_hbuf[pp][b1r * HDIM + jj]);
            }
        }

        float acc[3][2][4];
#pragma unroll
        for (int gi = 0; gi < 3; gi++)
#pragma unroll
            for (int jh = 0; jh < 2; jh++)
#pragma unroll
                for (int e = 0; e < 4; e++) acc[gi][jh][e] = 0.0f;

        // A-frag stream: base for this warp's (kh, mt); per-kb stride 512 u32.
        const unsigned* hfp = g_hfrag[pp] + (((kh * 32 * 4 + mt) * 32 + lane) << 2);
        uint4 a0 = __ldcg((const uint4*)hfp);
        uint4 a1 = __ldcg((const uint4*)(hfp + 512));

#pragma unroll 4
        for (int it = 0; it < 32; it++) {
            uint4 an = a1;
            if (it < 30) an = __ldcg((const uint4*)(hfp + (it + 2) * 512));
            const int kb = kh * 32 + it;
            const unsigned* wk = Whs + kb * 384 + lane * 2;
#pragma unroll
            for (int gi = 0; gi < 3; gi++)
#pragma unroll
                for (int jh = 0; jh < 2; jh++) {
                    uint2 b = *(const uint2*)(wk + (gi * 2 + jh) * 64);
                    mma_tf32_k8(acc[gi][jh], a0.x, a0.y, a0.z, a0.w, b.x, b.y);
                }
            a0 = a1; a1 = an;
        }

        // 4-way K reduction: kh1->buf0, kh3->buf1; kh0+=buf0, kh2+=buf1->buf1;
        // kh0+=buf1. Stride-25 float rows -> conflict-free scalar LDS/STS.
        if (kh & 1) {
            float* rp = red + ((kh >> 1) * 128 + mt * 32 + lane) * 25;
#pragma unroll
            for (int gi = 0; gi < 3; gi++)
#pragma unroll
                for (int jh = 0; jh < 2; jh++)
#pragma unroll
                    for (int e = 0; e < 4; e++) rp[gi * 8 + jh * 4 + e] = acc[gi][jh][e];
        }
        __syncthreads();
        if (kh == 0) {
            const float* rp = red + (mt * 32 + lane) * 25;
#pragma unroll
            for (int gi = 0; gi < 3; gi++)
#pragma unroll
                for (int jh = 0; jh < 2; jh++)
#pragma unroll
                    for (int e = 0; e < 4; e++) acc[gi][jh][e] += rp[gi * 8 + jh * 4 + e];
        } else if (kh == 2) {
            float* rp = red + (128 + mt * 32 + lane) * 25;
#pragma unroll
            for (int gi = 0; gi < 3; gi++)
#pragma unroll
                for (int jh = 0; jh < 2; jh++)
#pragma unroll
                    for (int e = 0; e < 4; e++) {
                        float v = acc[gi][jh][e] + rp[gi * 8 + jh * 4 + e];
                        rp[gi * 8 + jh * 4 + e] = v;
                    }
        }
        __syncthreads();

        if (kh == 0) {
            const float* rp = red + (128 + mt * 32 + lane) * 25;
            unsigned* nf = g_hfrag[pp ^ 1];
#pragma unroll
            for (int jh = 0; jh < 2; jh++) {
                const int jj = j0 + jh * 8 + 2 * c;
                float hy[4];
#pragma unroll
                for (int e = 0; e < 4; e++) {
                    int part = e & 1, row = e >> 1;
                    float pr = acc[0][jh][e] + rp[0 * 8 + jh * 4 + e] + bhv[0][jh][part];
                    float pu = acc[1][jh][e] + rp[1 * 8 + jh * 4 + e] + bhv[1][jh][part];
                    float pn = acc[2][jh][e] + rp[2 * 8 + jh * 4 + e] + bhv[2][jh][part];
                    float xr = part ? xv[0][jh][row].y : xv[0][jh][row].x;
                    float xu = part ? xv[1][jh][row].y : xv[1][jh][row].x;
                    float xn = part ? xv[2][jh][row].y : xv[2][jh][row].x;
                    float hpv = part ? hp[jh][row].y : hp[jh][row].x;
                    float rg = sigmoidf_(xr + pr);
                    float ug = sigmoidf_(xu + pu);
                    float ng = tanhf_(xn + rg * pn);
                    hy[e] = ug * hpv + (1.0f - ug) * ng;
                }
                // plain h (fp32) + hiddens output
                *(float2*)&g_hbuf[pp ^ 1][b0r * HDIM + jj] = make_float2(hy[0], hy[1]);
                *(float2*)&g_hbuf[pp ^ 1][b1r * HDIM + jj] = make_float2(hy[2], hy[3]);
                *(float2*)&hiddens[((size_t)b0r * TDIM + t) * HDIM + jj] = make_float2(hy[0], hy[1]);
                *(float2*)&hiddens[((size_t)b1r * TDIM + t) * HDIM + jj] = make_float2(hy[2], hy[3]);
                // fragment-major h (tf32) for next step's MMA
                const int kbt = blockIdx.x * 2 + jh;
#pragma unroll
                for (int e = 0; e < 4; e++) {
                    int part = e & 1, row = e >> 1;
                    int kpos = 2 * c + part;
                    int reg = row + 2 * (kpos >> 2);
                    int lnt = (g << 2) | (kpos & 3);
                    nf[(((kbt * 4 + mt) * 32 + lnt) << 2) + reg] = f2tf32(hy[e]);
                }
            }
        }

        // Global barrier (monotone counter; release via fence, acquire poll)
        __threadfence();
        __syncthreads();
        if (tid == 0) {
            atomicAdd((unsigned*)&g_count, 1u);
            unsigned target = (unsigned)(t + 1) * RCTA;
            unsigned v;
            do {
                asm volatile("ld.global.acquire.gpu.u32 %0, [%1];"
                             : "=r"(v) : "l"((const unsigned*)&g_count) : "memory");
            } while (v < target);
        }
        __syncthreads();
    }
}

__global__ void rec_init_kernel() {
    int i = blockIdx.x * blockDim.x + threadIdx.x;
    if (i == 0) g_count = 0;
    if (i < BDIM * HDIM) {
        g_hbuf[0][i] = 0.0f;
        g_hfrag[0][i] = 0u;
    }
}

extern "C" void kernel_launch(void* const* d_in, const int* in_sizes, int n_in,
                              void* d_out, int out_size)
{
    (void)in_sizes; (void)n_in; (void)out_size;
    const float* inputs = (const float*)d_in[0];
    const float* Wx = (const float*)d_in[1];
    const float* bx = (const float*)d_in[2];
    const float* Wh = (const float*)d_in[3];
    const float* bh = (const float*)d_in[4];
    const float* Wo = (const float*)d_in[5];
    const float* bo = (const float*)d_in[6];

    float* hiddens = (float*)d_out;                       // (B,T,H)
    float* proj    = hiddens + (size_t)MROWS * HDIM;      // (B,T,O)

    float* xall = nullptr;
    cudaGetSymbolAddress((void**)&xall, g_xall);

    // Phase 0: reset barrier + zero h0 (both layouts)
    rec_init_kernel<<<256, 256>>>();

    // Phase 1: x_all = inputs @ Wx^T + bx   (M=32768, N=3072, K=512)
    gemm_nt_kernel<<<dim3(G3 / 128, MROWS / 128), 256>>>(inputs, Wx, bx, xall, G3, DDIM);

    // Phase 2: persistent GRU recurrence -> hiddens (in d_out)
    const int rec_smem_bytes = 49152 * 4 + 6400 * 4;      // 222,208 B
    cudaFuncSetAttribute(gru_rec_kernel, cudaFuncAttributeMaxDynamicSharedMemorySize, rec_smem_bytes);
    gru_rec_kernel<<<RCTA, 512, rec_smem_bytes>>>(Wh, bh, hiddens);

    // Phase 3: out = hiddens @ Wo^T + bo   (M=32768, N=512, K=1024)
    gemm_nt_kernel<<<dim3(ODIM / 128, MROWS / 128), 256>>>(hiddens, Wo, bo, proj, ODIM, HDIM);
}